// round 11
// baseline (speedup 1.0000x reference)
#include <cuda_runtime.h>

#define SEQ   8192
#define HD    1024
#define G4    4096
#define NIN   64
#define NLAYER 5
#define NCTA  128

// ---------------- scratch (device globals; no allocation allowed) ------------
__device__ float    g_bufA[(size_t)SEQ * HD];   // activation ping
__device__ float    g_bufB[(size_t)SEQ * HD];   // activation pong
__device__ float    g_Z[(size_t)SEQ * G4];      // input projections (with bias)
__device__ float    g_h[2 * HD];                // double-buffered hidden state
__device__ unsigned g_flags[NCTA];              // per-CTA monotonic step flags

// ---------------- math helpers ----------------------------------------------
__device__ __forceinline__ float sigmf(float x) { return 1.0f / (1.0f + __expf(-x)); }
__device__ __forceinline__ float tanh_fast(float x) { return 1.0f - 2.0f / (__expf(2.0f * x) + 1.0f); }

__device__ __forceinline__ unsigned ld_acq(const unsigned* p) {
    unsigned v;
    asm volatile("ld.acquire.gpu.global.b32 %0, [%1];" : "=r"(v) : "l"(p) : "memory");
    return v;
}
__device__ __forceinline__ void st_rel(unsigned* p, unsigned v) {
    asm volatile("st.release.gpu.global.b32 [%0], %1;" :: "l"(p), "r"(v) : "memory");
}
__device__ __forceinline__ void st_rlx_f(float* p, float v) {
    asm volatile("st.relaxed.gpu.global.b32 [%0], %1;" :: "l"(p), "f"(v) : "memory");
}

// ---------------- init: flags = 0, seed layer-0 h_{-1} -----------------------
__global__ void k_init(const float* __restrict__ h0l) {
    const int i = threadIdx.x + blockIdx.x * blockDim.x;   // 0..1023
    if (i < NCTA) g_flags[i] = 0u;
    g_h[HD + i] = h0l[i];    // t=0 reads buf[1]
}

// ---------------- prep (layers >= 1): seed h_{-1} = h0[layer] ----------------
__global__ void k_prep(const float* __restrict__ h0l) {
    const int i = threadIdx.x + blockIdx.x * blockDim.x;
    if (i < HD) g_h[HD + i] = h0l[i];
}

// ---------------- first layer: leaky_relu(x @ w1^T + b1) ---------------------
__global__ __launch_bounds__(256) void k_first(const float* __restrict__ x,
                                               const float* __restrict__ w1,
                                               const float* __restrict__ b1,
                                               float* __restrict__ out) {
    __shared__ float xs[64][NIN];
    __shared__ float ws[64][NIN + 1];
    const int t0 = blockIdx.x * 64;
    const int h0 = blockIdx.y * 64;
    const int tid = threadIdx.x;

    for (int i = tid; i < 64 * NIN; i += 256)
        xs[i >> 6][i & 63] = x[(size_t)(t0 + (i >> 6)) * NIN + (i & 63)];
    for (int i = tid; i < 64 * NIN; i += 256)
        ws[i >> 6][i & 63] = w1[(size_t)(h0 + (i >> 6)) * NIN + (i & 63)];
    __syncthreads();

    const int h = tid & 63, tq = tid >> 6;
    float acc[16];
#pragma unroll
    for (int i = 0; i < 16; i++) acc[i] = 0.0f;

#pragma unroll 16
    for (int k = 0; k < NIN; k++) {
        const float wv = ws[h][k];
#pragma unroll
        for (int i = 0; i < 16; i++) acc[i] = fmaf(xs[tq * 16 + i][k], wv, acc[i]);
    }
    const float bb = b1[h0 + h];
#pragma unroll
    for (int i = 0; i < 16; i++) {
        float v = acc[i] + bb;
        v = (v >= 0.0f) ? v : 0.01f * v;
        out[(size_t)(t0 + tq * 16 + i) * HD + h0 + h] = v;
    }
}

// ---------------- input-projection GEMM: Z = X @ Wih^T + (b_ih + b_hh) -------
// R2-exact: 128x128x8 SGEMM, 256 threads, 8x8 accumulators, register prefetch.
__global__ __launch_bounds__(256, 2) void k_gemm(const float* __restrict__ A,   // (SEQ, HD)
                                                 const float* __restrict__ W,   // (G4, HD)
                                                 const float* __restrict__ bi,
                                                 const float* __restrict__ bh) {
    __shared__ float As[8][128];
    __shared__ float Bs[8][128];
    const int tid = threadIdx.x;
    const int tx = tid & 15, ty = tid >> 4;
    const int m0 = blockIdx.y * 128, n0 = blockIdx.x * 128;
    const int lr = tid >> 1, lk = (tid & 1) * 4;

    const float* Ap = A + (size_t)(m0 + lr) * HD + lk;
    const float* Wp = W + (size_t)(n0 + lr) * HD + lk;

    float acc[8][8];
#pragma unroll
    for (int i = 0; i < 8; i++)
#pragma unroll
        for (int j = 0; j < 8; j++) acc[i][j] = 0.0f;

    float4 av = *(const float4*)(Ap);
    float4 bv = *(const float4*)(Wp);

    for (int k0 = 0; k0 < HD; k0 += 8) {
        __syncthreads();
        As[lk + 0][lr] = av.x; As[lk + 1][lr] = av.y; As[lk + 2][lr] = av.z; As[lk + 3][lr] = av.w;
        Bs[lk + 0][lr] = bv.x; Bs[lk + 1][lr] = bv.y; Bs[lk + 2][lr] = bv.z; Bs[lk + 3][lr] = bv.w;
        __syncthreads();
        if (k0 + 8 < HD) {
            av = *(const float4*)(Ap + k0 + 8);
            bv = *(const float4*)(Wp + k0 + 8);
        }
#pragma unroll
        for (int kk = 0; kk < 8; kk++) {
            float ar[8], br[8];
            *(float4*)(ar)     = *(const float4*)&As[kk][ty * 8];
            *(float4*)(ar + 4) = *(const float4*)&As[kk][ty * 8 + 4];
            *(float4*)(br)     = *(const float4*)&Bs[kk][tx * 8];
            *(float4*)(br + 4) = *(const float4*)&Bs[kk][tx * 8 + 4];
#pragma unroll
            for (int i = 0; i < 8; i++)
#pragma unroll
                for (int j = 0; j < 8; j++) acc[i][j] = fmaf(ar[i], br[j], acc[i][j]);
        }
    }
    float bb[8];
#pragma unroll
    for (int j = 0; j < 8; j++) bb[j] = bi[n0 + tx * 8 + j] + bh[n0 + tx * 8 + j];
#pragma unroll
    for (int i = 0; i < 8; i++) {
        const size_t m = (size_t)(m0 + ty * 8 + i);
        float4 o0, o1;
        o0.x = acc[i][0] + bb[0]; o0.y = acc[i][1] + bb[1];
        o0.z = acc[i][2] + bb[2]; o0.w = acc[i][3] + bb[3];
        o1.x = acc[i][4] + bb[4]; o1.y = acc[i][5] + bb[5];
        o1.z = acc[i][6] + bb[6]; o1.w = acc[i][7] + bb[7];
        *(float4*)&g_Z[m * G4 + n0 + tx * 8]     = o0;
        *(float4*)&g_Z[m * G4 + n0 + tx * 8 + 4] = o1;
    }
}

// ---------------- recurrent persistent kernel --------------------------------
// R2 skeleton + two step-time cuts:
//  (1) z prefetched ONE STEP AHEAD (lanes 0-3, one gate each) -> DRAM hidden
//  (2) flag posted with st.release.gpu (no full membar drain)
__global__ __launch_bounds__(256, 1) void k_rec(const float* __restrict__ Whh,  // (G4, HD)
                                                const float* __restrict__ c0l,  // (HD)
                                                const float* __restrict__ Zin,  // (SEQ, G4)
                                                float* __restrict__ Xout,       // (SEQ, HD)
                                                unsigned base) {
    __shared__ float sh[2][HD];
    const int tid = threadIdx.x;
    const int w = tid >> 5, lane = tid & 31;
    const int u = blockIdx.x * 8 + w;

    unsigned sb;
    asm("{ .reg .u64 t; cvta.to.shared.u64 t, %1; cvt.u32.u64 %0, t; }"
        : "=r"(sb) : "l"((void*)sh));
    sb += (unsigned)lane * 8u;

    // packed weight pairs: lane owns k in {64j+2*lane, 64j+2*lane+1}
    unsigned long long wp[4][16];
#pragma unroll
    for (int g = 0; g < 4; g++) {
        const float* rp = Whh + (size_t)(g * HD + u) * HD + 2 * lane;
#pragma unroll
        for (int j = 0; j < 16; j++) {
            const float2 v = *(const float2*)(rp + 64 * j);
            asm("mov.b64 %0, {%1, %2};" : "=l"(wp[g][j]) : "f"(v.x), "f"(v.y));
        }
    }
    float c = c0l[u];   // only lane 0's copy is used

    // z for t=0, prefetched before the loop (lane g in [0,4) owns gate g)
    float zc = 0.f;
    if (lane < 4) zc = __ldcg(Zin + (size_t)lane * HD + u);

#pragma unroll 1
    for (int t = 0; t < SEQ; t++) {
        // wait only for the CTA producing THIS thread's float4 slice of h
        const unsigned target = base + (unsigned)t;
        {
            const unsigned* fp = &g_flags[tid >> 1];
            while (ld_acq(fp) < target) {}
            const float4 v = __ldcg((const float4*)(g_h + ((t + 1) & 1) * HD) + tid);
            *(float4*)&sh[t & 1][tid * 4] = v;
        }
        __syncthreads();

        // issue NEXT step's z load now: a full step (~2500 cyc) covers DRAM
        float zn = 0.f;
        if (lane < 4 && t + 1 < SEQ)
            zn = __ldcg(Zin + (size_t)(t + 1) * G4 + (size_t)lane * HD + u);

        // packed dot: 64 x fma.rn.f32x2 + 16 x LDS.64
        const unsigned sbase = sb + (unsigned)((t & 1) << 12);
        unsigned long long a0 = 0ull, a1 = 0ull, a2 = 0ull, a3 = 0ull;
#pragma unroll
        for (int j = 0; j < 16; j++) {
            unsigned long long hp;
            asm volatile("ld.shared.b64 %0, [%1];" : "=l"(hp) : "r"(sbase + (unsigned)(j * 256)));
            asm("fma.rn.f32x2 %0, %1, %2, %0;" : "+l"(a0) : "l"(wp[0][j]), "l"(hp));
            asm("fma.rn.f32x2 %0, %1, %2, %0;" : "+l"(a1) : "l"(wp[1][j]), "l"(hp));
            asm("fma.rn.f32x2 %0, %1, %2, %0;" : "+l"(a2) : "l"(wp[2][j]), "l"(hp));
            asm("fma.rn.f32x2 %0, %1, %2, %0;" : "+l"(a3) : "l"(wp[3][j]), "l"(hp));
        }
        float s0, s1, s2, s3;
        {
            float x, y;
            asm("mov.b64 {%0,%1}, %2;" : "=f"(x), "=f"(y) : "l"(a0)); s0 = x + y;
            asm("mov.b64 {%0,%1}, %2;" : "=f"(x), "=f"(y) : "l"(a1)); s1 = x + y;
            asm("mov.b64 {%0,%1}, %2;" : "=f"(x), "=f"(y) : "l"(a2)); s2 = x + y;
            asm("mov.b64 {%0,%1}, %2;" : "=f"(x), "=f"(y) : "l"(a3)); s3 = x + y;
        }
        // 4 interleaved shuffle trees (independent chains pipeline in the SMSP)
#pragma unroll
        for (int off = 16; off; off >>= 1) {
            s0 += __shfl_xor_sync(0xffffffffu, s0, off);
            s1 += __shfl_xor_sync(0xffffffffu, s1, off);
            s2 += __shfl_xor_sync(0xffffffffu, s2, off);
            s3 += __shfl_xor_sync(0xffffffffu, s3, off);
        }
        // 4 parallel activation chains on lanes 0-3 (z already lane-local)
        const float sg  = (lane == 0) ? s0 : (lane == 1) ? s1 : (lane == 2) ? s2 : s3;
        const float act = (lane == 2) ? tanh_fast(sg + zc) : sigmf(sg + zc);
        const float ig = __shfl_sync(0xffffffffu, act, 0);
        const float fg = __shfl_sync(0xffffffffu, act, 1);
        const float gg = __shfl_sync(0xffffffffu, act, 2);
        const float og = __shfl_sync(0xffffffffu, act, 3);
        float h = 0.f;
        if (lane == 0) {
            c = fg * c + ig * gg;
            h = og * tanh_fast(c);
            st_rlx_f(&g_h[(t & 1) * HD + u], h);    // strong store (gpu scope)
        }
        __syncthreads();                            // all h stores precede flag
        if (tid == 0)
            st_rel(&g_flags[blockIdx.x], target + 1u);   // release: publishes h
        if (lane == 0)
            Xout[(size_t)t * HD + u] = h;           // off the critical path
        zc = zn;
    }
}

// ---------------- final: tanh(leaky_relu(X) @ w2^T + b2) ---------------------
__global__ __launch_bounds__(256) void k_final(const float* __restrict__ Xin,
                                               const float* __restrict__ w2,   // (NIN, HD)
                                               const float* __restrict__ b2,
                                               float* __restrict__ y) {
    __shared__ float xs[64][65];
    __shared__ float ws[64][65];
    const int t0 = blockIdx.x * 64;
    const int tid = threadIdx.x;
    const int o = tid & 63, tq = tid >> 6;

    float acc[16];
#pragma unroll
    for (int i = 0; i < 16; i++) acc[i] = 0.0f;

    for (int k0 = 0; k0 < HD; k0 += 64) {
        __syncthreads();
        for (int i = tid; i < 64 * 64; i += 256) {
            const int r = i >> 6, cc = i & 63;
            float v = Xin[(size_t)(t0 + r) * HD + k0 + cc];
            xs[r][cc] = (v >= 0.0f) ? v : 0.01f * v;
            ws[r][cc] = w2[(size_t)r * HD + k0 + cc];
        }
        __syncthreads();
#pragma unroll 16
        for (int k = 0; k < 64; k++) {
            const float wv = ws[o][k];
#pragma unroll
            for (int i = 0; i < 16; i++) acc[i] = fmaf(xs[tq * 16 + i][k], wv, acc[i]);
        }
    }
    const float bb = b2[o];
#pragma unroll
    for (int i = 0; i < 16; i++)
        y[(size_t)(t0 + tq * 16 + i) * NIN + o] = tanh_fast(acc[i] + bb);
}

// ---------------- host launcher ----------------------------------------------
extern "C" void kernel_launch(void* const* d_in, const int* in_sizes, int n_in,
                              void* d_out, int out_size) {
    const float* data_in = (const float*)d_in[0];
    const float* w1      = (const float*)d_in[1];
    const float* b1      = (const float*)d_in[2];
    const float* W_ih    = (const float*)d_in[3];
    const float* W_hh    = (const float*)d_in[4];
    const float* b_ih    = (const float*)d_in[5];
    const float* b_hh    = (const float*)d_in[6];
    const float* w2      = (const float*)d_in[7];
    const float* b2      = (const float*)d_in[8];
    const float* h0      = (const float*)d_in[9];
    const float* c0      = (const float*)d_in[10];
    float* out = (float*)d_out;

    static float* dA = nullptr;
    static float* dB = nullptr;
    static float* dZ = nullptr;
    if (!dA) {   // host-side symbol queries; not allocations
        cudaGetSymbolAddress((void**)&dA, g_bufA);
        cudaGetSymbolAddress((void**)&dB, g_bufB);
        cudaGetSymbolAddress((void**)&dZ, g_Z);
    }
    float* bufs[2] = { dA, dB };

    k_init<<<4, 256>>>(h0);                                          // launch 1
    k_first<<<dim3(SEQ / 64, HD / 64), 256>>>(data_in, w1, b1, dA);  // launch 2

    for (int l = 0; l < NLAYER; l++) {
        const float* Xin = bufs[l & 1];
        float* Xout = bufs[(l & 1) ^ 1];
        if (l > 0)
            k_prep<<<4, 256>>>(h0 + (size_t)l * HD);
        k_gemm<<<dim3(G4 / 128, SEQ / 128), 256>>>(Xin,              // launch 3 (l=0)
                                                   W_ih + (size_t)l * G4 * HD,
                                                   b_ih + (size_t)l * G4,
                                                   b_hh + (size_t)l * G4);
        k_rec<<<NCTA, 256>>>(W_hh + (size_t)l * G4 * HD,             // launch 4 (l=0): profiled
                             c0 + (size_t)l * HD,
                             dZ,
                             Xout,
                             (unsigned)(l * SEQ));
    }
    k_final<<<SEQ / 64, 256>>>(bufs[NLAYER & 1], w2, b2, out);
}

// round 12
// speedup vs baseline: 3.2017x; 3.2017x over previous
#include <cuda_runtime.h>

#define SEQ   8192
#define HD    1024
#define G4    4096
#define NIN   64
#define NLAYER 5
#define NCTA  128
#define CH_CTAS 20
#define GRID_FAT (NCTA + CH_CTAS)   // 148 = one CTA per SM, rec gets exclusive SMs

// ---------------- scratch (device globals; no allocation allowed) ------------
__device__ float    g_bufA[(size_t)SEQ * HD];   // activation ping
__device__ float    g_bufB[(size_t)SEQ * HD];   // activation pong
__device__ float    g_Z0[(size_t)SEQ * G4];     // input-projection ping (bias included)
__device__ float    g_Z1[(size_t)SEQ * G4];     // input-projection pong (bias included)
__device__ float    g_h[2 * HD];                // double-buffered hidden state
__device__ unsigned g_flags[NCTA];              // per-CTA monotonic step flags

// ---------------- math helpers ----------------------------------------------
__device__ __forceinline__ float sigmf(float x) { return 1.0f / (1.0f + __expf(-x)); }
__device__ __forceinline__ float tanh_fast(float x) { return 1.0f - 2.0f / (__expf(2.0f * x) + 1.0f); }

__device__ __forceinline__ unsigned ld_acq(const unsigned* p) {
    unsigned v;
    asm volatile("ld.acquire.gpu.global.b32 %0, [%1];" : "=r"(v) : "l"(p) : "memory");
    return v;
}
__device__ __forceinline__ void st_relx(unsigned* p, unsigned v) {
    asm volatile("st.relaxed.gpu.global.b32 [%0], %1;" :: "l"(p), "r"(v) : "memory");
}

// ---------------- init: flags = 0, seed layer-0 h_{-1} -----------------------
__global__ void k_init(const float* __restrict__ h0l) {
    const int i = threadIdx.x + blockIdx.x * blockDim.x;   // 0..1023
    if (i < NCTA) g_flags[i] = 0u;
    g_h[HD + i] = h0l[i];    // t=0 reads buf[1]
}

// ---------------- prep (layers >= 1): seed h_{-1} = h0[layer] ----------------
__global__ void k_prep(const float* __restrict__ h0l) {
    const int i = threadIdx.x + blockIdx.x * blockDim.x;
    if (i < HD) g_h[HD + i] = h0l[i];
}

// ---------------- first layer: leaky_relu(x @ w1^T + b1) ---------------------
__global__ __launch_bounds__(256) void k_first(const float* __restrict__ x,
                                               const float* __restrict__ w1,
                                               const float* __restrict__ b1,
                                               float* __restrict__ out) {
    __shared__ float xs[64][NIN];
    __shared__ float ws[64][NIN + 1];
    const int t0 = blockIdx.x * 64;
    const int h0 = blockIdx.y * 64;
    const int tid = threadIdx.x;

    for (int i = tid; i < 64 * NIN; i += 256)
        xs[i >> 6][i & 63] = x[(size_t)(t0 + (i >> 6)) * NIN + (i & 63)];
    for (int i = tid; i < 64 * NIN; i += 256)
        ws[i >> 6][i & 63] = w1[(size_t)(h0 + (i >> 6)) * NIN + (i & 63)];
    __syncthreads();

    const int h = tid & 63, tq = tid >> 6;
    float acc[16];
#pragma unroll
    for (int i = 0; i < 16; i++) acc[i] = 0.0f;

#pragma unroll 16
    for (int k = 0; k < NIN; k++) {
        const float wv = ws[h][k];
#pragma unroll
        for (int i = 0; i < 16; i++) acc[i] = fmaf(xs[tq * 16 + i][k], wv, acc[i]);
    }
    const float bb = b1[h0 + h];
#pragma unroll
    for (int i = 0; i < 16; i++) {
        float v = acc[i] + bb;
        v = (v >= 0.0f) ? v : 0.01f * v;
        out[(size_t)(t0 + tq * 16 + i) * HD + h0 + h] = v;
    }
}

// ---------------- layer-0 input GEMM: Z = X @ Wih^T + (b_ih + b_hh) ----------
// R2-exact: 128x128x8 SGEMM, 256 threads, 8x8 accumulators, register prefetch.
__global__ __launch_bounds__(256, 2) void k_gemm(const float* __restrict__ A,   // (SEQ, HD)
                                                 const float* __restrict__ W,   // (G4, HD)
                                                 const float* __restrict__ bi,
                                                 const float* __restrict__ bh,
                                                 float* __restrict__ Z) {
    __shared__ float As[8][128];
    __shared__ float Bs[8][128];
    const int tid = threadIdx.x;
    const int tx = tid & 15, ty = tid >> 4;
    const int m0 = blockIdx.y * 128, n0 = blockIdx.x * 128;
    const int lr = tid >> 1, lk = (tid & 1) * 4;

    const float* Ap = A + (size_t)(m0 + lr) * HD + lk;
    const float* Wp = W + (size_t)(n0 + lr) * HD + lk;

    float acc[8][8];
#pragma unroll
    for (int i = 0; i < 8; i++)
#pragma unroll
        for (int j = 0; j < 8; j++) acc[i][j] = 0.0f;

    float4 av = *(const float4*)(Ap);
    float4 bv = *(const float4*)(Wp);

    for (int k0 = 0; k0 < HD; k0 += 8) {
        __syncthreads();
        As[lk + 0][lr] = av.x; As[lk + 1][lr] = av.y; As[lk + 2][lr] = av.z; As[lk + 3][lr] = av.w;
        Bs[lk + 0][lr] = bv.x; Bs[lk + 1][lr] = bv.y; Bs[lk + 2][lr] = bv.z; Bs[lk + 3][lr] = bv.w;
        __syncthreads();
        if (k0 + 8 < HD) {
            av = *(const float4*)(Ap + k0 + 8);
            bv = *(const float4*)(Wp + k0 + 8);
        }
#pragma unroll
        for (int kk = 0; kk < 8; kk++) {
            float ar[8], br[8];
            *(float4*)(ar)     = *(const float4*)&As[kk][ty * 8];
            *(float4*)(ar + 4) = *(const float4*)&As[kk][ty * 8 + 4];
            *(float4*)(br)     = *(const float4*)&Bs[kk][tx * 8];
            *(float4*)(br + 4) = *(const float4*)&Bs[kk][tx * 8 + 4];
#pragma unroll
            for (int i = 0; i < 8; i++)
#pragma unroll
                for (int j = 0; j < 8; j++) acc[i][j] = fmaf(ar[i], br[j], acc[i][j]);
        }
    }
    float bb[8];
#pragma unroll
    for (int j = 0; j < 8; j++) bb[j] = bi[n0 + tx * 8 + j] + bh[n0 + tx * 8 + j];
#pragma unroll
    for (int i = 0; i < 8; i++) {
        const size_t m = (size_t)(m0 + ty * 8 + i);
        float4 o0, o1;
        o0.x = acc[i][0] + bb[0]; o0.y = acc[i][1] + bb[1];
        o0.z = acc[i][2] + bb[2]; o0.w = acc[i][3] + bb[3];
        o1.x = acc[i][4] + bb[4]; o1.y = acc[i][5] + bb[5];
        o1.z = acc[i][6] + bb[6]; o1.w = acc[i][7] + bb[7];
        *(float4*)&Z[m * G4 + n0 + tx * 8]     = o0;
        *(float4*)&Z[m * G4 + n0 + tx * 8 + 4] = o1;
    }
}

// ---------------- fat kernel: rec on SMs 0..127, chase GEMM on the 20 idle SMs
// rec (bid < 128): R2-EXACT inner loop (frozen). Only change: Xout stored
//   before the barrier so fence+flag also publish X_l to chase readers.
// chase (bid >= 128): Z_{l+1} = X_l @ Wih_{l+1}^T + bias, 128x128 tiles in
//   m-major order, strided over 20 CTAs; tile waits until all 128 step flags
//   cover its 128 timesteps. grid=148 -> one CTA/SM -> zero SMSP interference.
__global__ __launch_bounds__(256, 1) void k_rec(const float* __restrict__ Whh,  // (G4, HD)
                                                const float* __restrict__ c0l,  // (HD)
                                                const float* __restrict__ Zin,  // (SEQ, G4)
                                                float* __restrict__ Xout,       // (SEQ, HD)
                                                const float* __restrict__ Wn,   // Wih_{l+1}
                                                const float* __restrict__ bi2,  // b_ih[l+1]
                                                const float* __restrict__ bh2,  // b_hh[l+1]
                                                float* __restrict__ Zout,       // (SEQ, G4)
                                                unsigned base, int fuse) {
    __shared__ float sh[2][HD];                  // rec: h staging | chase: As/Bs
    const int tid = threadIdx.x;

    if (blockIdx.x < NCTA) {
        // ======================= rec (R2-exact) =======================
        const int w = tid >> 5, lane = tid & 31;
        const int u = blockIdx.x * 8 + w;

        unsigned sb;
        asm("{ .reg .u64 t; cvta.to.shared.u64 t, %1; cvt.u32.u64 %0, t; }"
            : "=r"(sb) : "l"((void*)sh));
        sb += (unsigned)lane * 8u;

        unsigned long long wp[4][16];
#pragma unroll
        for (int g = 0; g < 4; g++) {
            const float* rp = Whh + (size_t)(g * HD + u) * HD + 2 * lane;
#pragma unroll
            for (int j = 0; j < 16; j++) {
                const float2 v = *(const float2*)(rp + 64 * j);
                asm("mov.b64 %0, {%1, %2};" : "=l"(wp[g][j]) : "f"(v.x), "f"(v.y));
            }
        }
        float c = c0l[u];   // only lane 0's copy is used

#pragma unroll 1
        for (int t = 0; t < SEQ; t++) {
            float z0 = 0.f, z1 = 0.f, z2 = 0.f, z3 = 0.f;
            if (lane == 0) {
                const float* zp = Zin + (size_t)t * G4 + u;
                z0 = zp[0]; z1 = zp[HD]; z2 = zp[2 * HD]; z3 = zp[3 * HD];
            }
            const unsigned target = base + (unsigned)t;
            {
                const unsigned* fp = &g_flags[tid >> 1];
                while (ld_acq(fp) < target) {}
                const float4 v = __ldcg((const float4*)(g_h + ((t + 1) & 1) * HD) + tid);
                *(float4*)&sh[t & 1][tid * 4] = v;
            }
            __syncthreads();

            const unsigned sbase = sb + (unsigned)((t & 1) << 12);
            unsigned long long a0 = 0ull, a1 = 0ull, a2 = 0ull, a3 = 0ull;
#pragma unroll
            for (int j = 0; j < 16; j++) {
                unsigned long long hp;
                asm volatile("ld.shared.b64 %0, [%1];" : "=l"(hp) : "r"(sbase + (unsigned)(j * 256)));
                asm("fma.rn.f32x2 %0, %1, %2, %0;" : "+l"(a0) : "l"(wp[0][j]), "l"(hp));
                asm("fma.rn.f32x2 %0, %1, %2, %0;" : "+l"(a1) : "l"(wp[1][j]), "l"(hp));
                asm("fma.rn.f32x2 %0, %1, %2, %0;" : "+l"(a2) : "l"(wp[2][j]), "l"(hp));
                asm("fma.rn.f32x2 %0, %1, %2, %0;" : "+l"(a3) : "l"(wp[3][j]), "l"(hp));
            }
            float s0, s1, s2, s3;
            {
                float x, y;
                asm("mov.b64 {%0,%1}, %2;" : "=f"(x), "=f"(y) : "l"(a0)); s0 = x + y;
                asm("mov.b64 {%0,%1}, %2;" : "=f"(x), "=f"(y) : "l"(a1)); s1 = x + y;
                asm("mov.b64 {%0,%1}, %2;" : "=f"(x), "=f"(y) : "l"(a2)); s2 = x + y;
                asm("mov.b64 {%0,%1}, %2;" : "=f"(x), "=f"(y) : "l"(a3)); s3 = x + y;
            }
#pragma unroll
            for (int off = 16; off; off >>= 1) {
                s0 += __shfl_xor_sync(0xffffffffu, s0, off);
                s1 += __shfl_xor_sync(0xffffffffu, s1, off);
                s2 += __shfl_xor_sync(0xffffffffu, s2, off);
                s3 += __shfl_xor_sync(0xffffffffu, s3, off);
            }
            if (lane == 0) {
                const float ig = sigmf(s0 + z0);
                const float fg = sigmf(s1 + z1);
                const float gg = tanh_fast(s2 + z2);
                const float og = sigmf(s3 + z3);
                c = fg * c + ig * gg;
                const float h = og * tanh_fast(c);
                __stcg(&g_h[(t & 1) * HD + u], h);  // broadcast buffer (L2)
                Xout[(size_t)t * HD + u] = h;       // pre-bar: fence+flag publish it
            }
            __syncthreads();                        // all h/X stores precede fence
            if (tid == 0) {
                __threadfence();                    // publish h + X (cumulative)
                st_relx(&g_flags[blockIdx.x], target + 1u);
            }
        }
    } else {
        // ======================= chase GEMM =======================
        if (!fuse) return;
        const int cb = blockIdx.x - NCTA;            // 0..19
        const int tx = tid & 15, ty = tid >> 4;
        const int lr = tid >> 1, lk = (tid & 1) * 4;
        float* As = &sh[0][0];                       // [8][128]
        float* Bs = &sh[1][0];                       // [8][128]

        for (int tile = cb; tile < (SEQ / 128) * (G4 / 128); tile += CH_CTAS) {
            const int m0 = (tile >> 5) << 7;         // m-major order
            const int n0 = (tile & 31) << 7;
            const unsigned need = base + (unsigned)(m0 + 128);
            while (ld_acq(&g_flags[tid & 127]) < need) __nanosleep(1024);
            __syncthreads();

            const float* Ap = Xout + (size_t)(m0 + lr) * HD + lk;
            const float* Wp = Wn + (size_t)(n0 + lr) * HD + lk;

            float acc[8][8];
#pragma unroll
            for (int i = 0; i < 8; i++)
#pragma unroll
                for (int j = 0; j < 8; j++) acc[i][j] = 0.0f;

            float4 av = *(const float4*)(Ap);
            float4 bv = *(const float4*)(Wp);

            for (int k0 = 0; k0 < HD; k0 += 8) {
                __syncthreads();
                As[(lk + 0) * 128 + lr] = av.x; As[(lk + 1) * 128 + lr] = av.y;
                As[(lk + 2) * 128 + lr] = av.z; As[(lk + 3) * 128 + lr] = av.w;
                Bs[(lk + 0) * 128 + lr] = bv.x; Bs[(lk + 1) * 128 + lr] = bv.y;
                Bs[(lk + 2) * 128 + lr] = bv.z; Bs[(lk + 3) * 128 + lr] = bv.w;
                __syncthreads();
                if (k0 + 8 < HD) {
                    av = *(const float4*)(Ap + k0 + 8);
                    bv = *(const float4*)(Wp + k0 + 8);
                }
#pragma unroll
                for (int kk = 0; kk < 8; kk++) {
                    float ar[8], br[8];
                    *(float4*)(ar)     = *(const float4*)&As[kk * 128 + ty * 8];
                    *(float4*)(ar + 4) = *(const float4*)&As[kk * 128 + ty * 8 + 4];
                    *(float4*)(br)     = *(const float4*)&Bs[kk * 128 + tx * 8];
                    *(float4*)(br + 4) = *(const float4*)&Bs[kk * 128 + tx * 8 + 4];
#pragma unroll
                    for (int i = 0; i < 8; i++)
#pragma unroll
                        for (int j = 0; j < 8; j++) acc[i][j] = fmaf(ar[i], br[j], acc[i][j]);
                }
            }
            float bb[8];
#pragma unroll
            for (int j = 0; j < 8; j++) bb[j] = bi2[n0 + tx * 8 + j] + bh2[n0 + tx * 8 + j];
#pragma unroll
            for (int i = 0; i < 8; i++) {
                const size_t m = (size_t)(m0 + ty * 8 + i);
                float4 o0, o1;
                o0.x = acc[i][0] + bb[0]; o0.y = acc[i][1] + bb[1];
                o0.z = acc[i][2] + bb[2]; o0.w = acc[i][3] + bb[3];
                o1.x = acc[i][4] + bb[4]; o1.y = acc[i][5] + bb[5];
                o1.z = acc[i][6] + bb[6]; o1.w = acc[i][7] + bb[7];
                *(float4*)&Zout[m * G4 + n0 + tx * 8]     = o0;
                *(float4*)&Zout[m * G4 + n0 + tx * 8 + 4] = o1;
            }
            __syncthreads();   // smem safe before next tile's stores
        }
    }
}

// ---------------- final: tanh(leaky_relu(X) @ w2^T + b2) ---------------------
__global__ __launch_bounds__(256) void k_final(const float* __restrict__ Xin,
                                               const float* __restrict__ w2,   // (NIN, HD)
                                               const float* __restrict__ b2,
                                               float* __restrict__ y) {
    __shared__ float xs[64][65];
    __shared__ float ws[64][65];
    const int t0 = blockIdx.x * 64;
    const int tid = threadIdx.x;
    const int o = tid & 63, tq = tid >> 6;

    float acc[16];
#pragma unroll
    for (int i = 0; i < 16; i++) acc[i] = 0.0f;

    for (int k0 = 0; k0 < HD; k0 += 64) {
        __syncthreads();
        for (int i = tid; i < 64 * 64; i += 256) {
            const int r = i >> 6, cc = i & 63;
            float v = Xin[(size_t)(t0 + r) * HD + k0 + cc];
            xs[r][cc] = (v >= 0.0f) ? v : 0.01f * v;
            ws[r][cc] = w2[(size_t)r * HD + k0 + cc];
        }
        __syncthreads();
#pragma unroll 16
        for (int k = 0; k < 64; k++) {
            const float wv = ws[o][k];
#pragma unroll
            for (int i = 0; i < 16; i++) acc[i] = fmaf(xs[tq * 16 + i][k], wv, acc[i]);
        }
    }
    const float bb = b2[o];
#pragma unroll
    for (int i = 0; i < 16; i++)
        y[(size_t)(t0 + tq * 16 + i) * NIN + o] = tanh_fast(acc[i] + bb);
}

// ---------------- host launcher (single stream) -------------------------------
extern "C" void kernel_launch(void* const* d_in, const int* in_sizes, int n_in,
                              void* d_out, int out_size) {
    const float* data_in = (const float*)d_in[0];
    const float* w1      = (const float*)d_in[1];
    const float* b1      = (const float*)d_in[2];
    const float* W_ih    = (const float*)d_in[3];
    const float* W_hh    = (const float*)d_in[4];
    const float* b_ih    = (const float*)d_in[5];
    const float* b_hh    = (const float*)d_in[6];
    const float* w2      = (const float*)d_in[7];
    const float* b2      = (const float*)d_in[8];
    const float* h0      = (const float*)d_in[9];
    const float* c0      = (const float*)d_in[10];
    float* out = (float*)d_out;

    static float* dA = nullptr;
    static float* dB = nullptr;
    static float* dZ0 = nullptr;
    static float* dZ1 = nullptr;
    if (!dA) {   // host-side symbol queries; not allocations
        cudaGetSymbolAddress((void**)&dA, g_bufA);
        cudaGetSymbolAddress((void**)&dB, g_bufB);
        cudaGetSymbolAddress((void**)&dZ0, g_Z0);
        cudaGetSymbolAddress((void**)&dZ1, g_Z1);
    }
    float* bufs[2] = { dA, dB };
    float* zbuf[2] = { dZ0, dZ1 };

    k_init<<<4, 256>>>(h0);                                            // 1
    k_first<<<dim3(SEQ / 64, HD / 64), 256>>>(data_in, w1, b1, dA);    // 2
    k_gemm<<<dim3(G4 / 128, SEQ / 128), 256>>>(dA, W_ih,               // 3: layer-0 Z
                                               b_ih, b_hh, dZ0);

    for (int l = 0; l < NLAYER; l++) {
        float* Xl = bufs[(l + 1) & 1];      // rec(l) output sequence
        const int fuse = (l < NLAYER - 1) ? 1 : 0;
        if (l > 0)
            k_prep<<<4, 256>>>(h0 + (size_t)l * HD);
        k_rec<<<GRID_FAT, 256>>>(W_hh + (size_t)l * G4 * HD,           // 4 (l=0): profiled
                                 c0 + (size_t)l * HD,
                                 zbuf[l & 1],
                                 Xl,
                                 W_ih + (size_t)(fuse ? (l + 1) : l) * G4 * HD,
                                 b_ih + (size_t)(fuse ? (l + 1) : l) * G4,
                                 b_hh + (size_t)(fuse ? (l + 1) : l) * G4,
                                 zbuf[(l + 1) & 1],
                                 (unsigned)(l * SEQ), fuse);
    }
    k_final<<<SEQ / 64, 256>>>(bufs[NLAYER & 1], w2, b2, out);
}